// round 14
// baseline (speedup 1.0000x reference)
#include <cuda_runtime.h>
#include <cuda_bf16.h>
#include <cstdint>
#include <cstddef>

#define DEV_INLINE __device__ __forceinline__

namespace {
constexpr int kB    = 64;
constexpr int kT    = 512;
constexpr int kDin  = 512;
constexpr int kDh   = 1024;
constexpr int kDout = 1024;
constexpr int kNC   = 128;       // persistent CTA count (<=148 SMs, co-resident)
constexpr int kKP   = kDh / 2;   // 512 k-pairs (recurrent K)
constexpr int kKPx  = kDin / 2;  // 256 k-pairs (input K)
constexpr int kKS   = kKP / 8;   // 64 k-chunks (16 elems each)
constexpr int CPA   = 33;        // padded col stride, phase A smem B (32 cols)
constexpr int CPB   = 17;        // padded col stride, phase B smem B (16 cols)
constexpr int kSmemA4 = kKS * 4 * CPA;              // uint4 count (135168 B)
constexpr int kSmemB4 = kKS * 4 * CPB;              // (69632 B)
constexpr int kRedFloats = 4 * 32 * 32;             // 4 layers x 32 slots x 32 lanes (16 KB)
constexpr size_t kSmemBytes = (size_t)(kSmemA4 + kSmemB4) * 16 + kRedFloats * 4; // 221184
}

// ---------------- device scratch (no allocs allowed) ------------------------
__device__ float g_xbuf[(size_t)kT * 3 * kB * kDh];   // [t][gate][b][j], x-proj + bias
__device__ float g_hs[(size_t)(kT + 1) * kB * kDh];   // [t][b][j]
__device__ float g_z[(size_t)kB * kDh];               // z gate (per step)
// packed GEMM-A operands, uint4 = { pk(8ks+q).hi, .lo, pk(8ks+q+4).hi, .lo }
__device__ uint4 g_hpk4[(size_t)kB * kKS * 4];        // current h packed
__device__ uint4 g_rhpk4[(size_t)kB * kKS * 4];       // r*h packed
__device__ uint2 g_wpk[(size_t)3 * kDh * kKP];        // W*_h packed, [gate][j][kp]
// pre-packed operands for the parallel GEMMs
__device__ uint2 g_inpk[(size_t)kB * kT * kKPx];      // inputs packed [row=b*T+t][kp]
__device__ uint2 g_wxpk[(size_t)3 * kDh * kKPx];      // W*_x packed [gate][j][kp]
__device__ uint2 g_wopk[(size_t)kDout * kKP];         // Wo packed [o][kp]
__device__ uint2 g_hspk[(size_t)kT * kB * kKP];       // h history packed [t][b][kp]
// flag-array grid barrier (reset by zero_h0_kernel each launch)
__device__ unsigned g_flags[kNC * 32];                // one 128B line per CTA
__device__ unsigned g_bar_gen = 0;

// ---------------- bf16 split helpers ----------------------------------------

DEV_INLINE void split2(float x0, float x1, uint32_t& hi, uint32_t& lo) {
    __nv_bfloat16 h0 = __float2bfloat16_rn(x0);
    __nv_bfloat16 h1 = __float2bfloat16_rn(x1);
    __nv_bfloat16 l0 = __float2bfloat16_rn(x0 - __bfloat162float(h0));
    __nv_bfloat16 l1 = __float2bfloat16_rn(x1 - __bfloat162float(h1));
    hi = (uint32_t)__bfloat16_as_ushort(h0) | ((uint32_t)__bfloat16_as_ushort(h1) << 16);
    lo = (uint32_t)__bfloat16_as_ushort(l0) | ((uint32_t)__bfloat16_as_ushort(l1) << 16);
}

// D += A(16x16, row) * B(16x8, col), bf16 in, fp32 accum
DEV_INLINE void mma16(float c[4], const uint32_t a[4], const uint32_t b[2]) {
    asm volatile(
        "mma.sync.aligned.m16n8k16.row.col.f32.bf16.bf16.f32 "
        "{%0,%1,%2,%3}, {%4,%5,%6,%7}, {%8,%9}, {%0,%1,%2,%3};\n"
        : "+f"(c[0]), "+f"(c[1]), "+f"(c[2]), "+f"(c[3])
        : "r"(a[0]), "r"(a[1]), "r"(a[2]), "r"(a[3]), "r"(b[0]), "r"(b[1]));
}

DEV_INLINE float sigmoidf_(float x) { return 1.0f / (1.0f + __expf(-x)); }

// ---------------- init (also resets barrier state each launch) ---------------

__global__ void zero_h0_kernel() {
    int i = blockIdx.x * blockDim.x + threadIdx.x;
    if (i < kB * kDh) g_hs[i] = 0.0f;
    if (i < kB * kKS * 4) g_hpk4[i] = make_uint4(0u, 0u, 0u, 0u);
    if (i < kNC) g_flags[i * 32] = 0u;
    if (i == 0) g_bar_gen = 0u;
}

// ---------------- packers ----------------------------------------------------

__global__ void prep_w_kernel(const float* __restrict__ Wz,
                              const float* __restrict__ Wr,
                              const float* __restrict__ Ws) {
    size_t i = (size_t)blockIdx.x * blockDim.x + threadIdx.x;
    if (i >= (size_t)3 * kKP * kDh) return;
    int j  = (int)(i & (kDh - 1));
    int kp = (int)((i >> 10) & (kKP - 1));
    int g  = (int)(i >> 19);
    const float* W = (g == 0) ? Wz : (g == 1) ? Wr : Ws;
    uint32_t hi, lo;
    split2(W[(size_t)(2 * kp) * kDh + j], W[(size_t)(2 * kp + 1) * kDh + j], hi, lo);
    g_wpk[((size_t)g * kDh + j) * kKP + kp] = make_uint2(hi, lo);
}

__global__ void prep_wx_kernel(const float* __restrict__ Wz,
                               const float* __restrict__ Wr,
                               const float* __restrict__ Ws) {
    size_t i = (size_t)blockIdx.x * blockDim.x + threadIdx.x;
    if (i >= (size_t)3 * kDh * kKPx) return;
    int kp = (int)(i & (kKPx - 1));
    int j  = (int)((i >> 8) & (kDh - 1));
    int g  = (int)(i >> 18);
    const float* W = (g == 0) ? Wz : (g == 1) ? Wr : Ws;
    uint32_t hi, lo;
    split2(W[(size_t)(kDh + 2 * kp) * kDh + j],
           W[(size_t)(kDh + 2 * kp + 1) * kDh + j], hi, lo);
    g_wxpk[((size_t)g * kDh + j) * kKPx + kp] = make_uint2(hi, lo);
}

__global__ void prep_wo_kernel(const float* __restrict__ Wo) {
    size_t i = (size_t)blockIdx.x * blockDim.x + threadIdx.x;
    if (i >= (size_t)kDout * kKP) return;
    int kp = (int)(i & (kKP - 1));
    int o  = (int)(i >> 9);
    uint32_t hi, lo;
    split2(Wo[(size_t)(2 * kp) * kDout + o], Wo[(size_t)(2 * kp + 1) * kDout + o], hi, lo);
    g_wopk[(size_t)o * kKP + kp] = make_uint2(hi, lo);
}

__global__ void prep_in_kernel(const float* __restrict__ inp) {
    size_t i = (size_t)blockIdx.x * blockDim.x + threadIdx.x;
    if (i >= (size_t)kB * kT * kKPx) return;
    const float2 v = *reinterpret_cast<const float2*>(inp + 2 * i);
    uint32_t hi, lo;
    split2(v.x, v.y, hi, lo);
    g_inpk[i] = make_uint2(hi, lo);
}

// ---------------- x-projections (packed operands, pure GEMM) -----------------

__global__ void proj_x_kernel(const float* __restrict__ bz,
                              const float* __restrict__ br,
                              const float* __restrict__ bs) {
    const int r0   = blockIdx.x * 64;
    const int c0   = blockIdx.y * 64;
    const int gate = c0 >> 10;
    const int jg0  = c0 & (kDh - 1);
    const float* __restrict__ bias = (gate == 0) ? bz : (gate == 1) ? br : bs;

    __shared__ uint32_t Ah[64][17], Al[64][17];
    __shared__ uint32_t Bh[64][17], Bl[64][17];

    const int tid = threadIdx.x;
    const int wid = tid >> 5, lane = tid & 31;
    const int wm  = (wid & 3) * 16;
    const int wn  = (wid >> 2) * 32;
    const int grp = lane >> 2, tg = lane & 3;

    const uint2* __restrict__ Bw = g_wxpk + (size_t)gate * kDh * kKPx;

    float acc[4][4] = {};

    for (int kp0 = 0; kp0 < kKPx; kp0 += 16) {
        for (int idx = tid; idx < 64 * 16; idx += 256) {
            int kp = idx & 15, m = idx >> 4;
            uint2 v = g_inpk[(size_t)(r0 + m) * kKPx + kp0 + kp];
            Ah[m][kp] = v.x; Al[m][kp] = v.y;
        }
        for (int idx = tid; idx < 64 * 16; idx += 256) {
            int kp = idx & 15, j = idx >> 4;
            uint2 v = Bw[(size_t)(jg0 + j) * kKPx + kp0 + kp];
            Bh[j][kp] = v.x; Bl[j][kp] = v.y;
        }
        __syncthreads();
#pragma unroll
        for (int kt = 0; kt < 2; kt++) {
            uint32_t ah[4], al[4];
            ah[0] = Ah[wm + grp][kt * 8 + tg];         al[0] = Al[wm + grp][kt * 8 + tg];
            ah[1] = Ah[wm + grp + 8][kt * 8 + tg];     al[1] = Al[wm + grp + 8][kt * 8 + tg];
            ah[2] = Ah[wm + grp][kt * 8 + tg + 4];     al[2] = Al[wm + grp][kt * 8 + tg + 4];
            ah[3] = Ah[wm + grp + 8][kt * 8 + tg + 4]; al[3] = Al[wm + grp + 8][kt * 8 + tg + 4];
#pragma unroll
            for (int nt = 0; nt < 4; nt++) {
                const int jj = wn + nt * 8 + grp;
                uint32_t bh[2], bl[2];
                bh[0] = Bh[jj][kt * 8 + tg];     bl[0] = Bl[jj][kt * 8 + tg];
                bh[1] = Bh[jj][kt * 8 + tg + 4]; bl[1] = Bl[jj][kt * 8 + tg + 4];
                mma16(acc[nt], ah, bh);
                mma16(acc[nt], ah, bl);
                mma16(acc[nt], al, bh);
            }
        }
        __syncthreads();
    }

#pragma unroll
    for (int nt = 0; nt < 4; nt++) {
#pragma unroll
        for (int cc = 0; cc < 4; cc++) {
            int row = r0 + wm + grp + ((cc & 2) ? 8 : 0);
            int col = jg0 + wn + nt * 8 + 2 * tg + (cc & 1);
            int b = row >> 9;
            int t = row & (kT - 1);
            g_xbuf[(((size_t)t * 3 + gate) * kB + b) * kDh + col] = acc[nt][cc] + bias[col];
        }
    }
}

// ---------------- flag-array grid barrier ------------------------------------
// Each CTA releases its own flag; CTA 0 aggregates (1 thread per flag) and
// releases g_bar_gen; others poll g_bar_gen. target increases per call.

DEV_INLINE void grid_barrier(int cta, unsigned target) {
    __syncthreads();
    if (cta == 0) {
        if (threadIdx.x < kNC) {
            if (threadIdx.x == 0)
                asm volatile("st.release.gpu.global.u32 [%0], %1;"
                             :: "l"(&g_flags[0]), "r"(target));
            unsigned v;
            do {
                asm volatile("ld.acquire.gpu.global.u32 %0, [%1];"
                             : "=r"(v) : "l"(&g_flags[threadIdx.x * 32]));
            } while (v < target);
        }
        __syncthreads();
        if (threadIdx.x == 0)
            asm volatile("st.release.gpu.global.u32 [%0], %1;"
                         :: "l"(&g_bar_gen), "r"(target));
    } else {
        if (threadIdx.x == 0) {
            asm volatile("st.release.gpu.global.u32 [%0], %1;"
                         :: "l"(&g_flags[cta * 32]), "r"(target));
            unsigned v;
            do {
                asm volatile("ld.acquire.gpu.global.u32 %0, [%1];"
                             : "=r"(v) : "l"(&g_bar_gen));
            } while (v < target);
        }
        __syncthreads();
    }
}

// ---------------- GEMM core: warp m16 x (NT*8), 8 k-chunks, B from smem ------
// 2 accumulator chains (hh+lh merged into c1, hl in c2) to fit 128 regs @512thr.

template <int NT, int CPAD>
DEV_INLINE void gemm8(const uint4* __restrict__ A4, const uint4* __restrict__ Bs,
                      int ks0, int r0, int r1, int grp, int tg, float out[NT][4]) {
    const uint4* __restrict__ r0p = A4 + (size_t)r0 * (kKS * 4) + tg;
    const uint4* __restrict__ r1p = A4 + (size_t)r1 * (kKS * 4) + tg;

    float c1[NT][4], c2[NT][4];
#pragma unroll
    for (int nt = 0; nt < NT; nt++)
#pragma unroll
        for (int i = 0; i < 4; i++) { c1[nt][i] = 0.f; c2[nt][i] = 0.f; }

    uint4 abuf[2][2];
    abuf[0][0] = r0p[ks0 * 4];        abuf[0][1] = r1p[ks0 * 4];
    abuf[1][0] = r0p[(ks0 + 1) * 4];  abuf[1][1] = r1p[(ks0 + 1) * 4];

#pragma unroll
    for (int s = 0; s < 8; s++) {
        const int ks = ks0 + s;
        const uint4 a0 = abuf[s & 1][0];
        const uint4 a1 = abuf[s & 1][1];
        if (s + 2 < 8) {
            abuf[s & 1][0] = r0p[(ks + 2) * 4];
            abuf[s & 1][1] = r1p[(ks + 2) * 4];
        }
        uint4 bq[NT];
        const uint4* __restrict__ brow = Bs + (ks * 4 + tg) * CPAD + grp;
#pragma unroll
        for (int nt = 0; nt < NT; nt++) bq[nt] = brow[nt * 8];

        const uint32_t ah[4] = {a0.x, a1.x, a0.z, a1.z};
        const uint32_t al[4] = {a0.y, a1.y, a0.w, a1.w};
#pragma unroll
        for (int nt = 0; nt < NT; nt++) {
            const uint32_t bh[2] = {bq[nt].x, bq[nt].z};
            const uint32_t bl[2] = {bq[nt].y, bq[nt].w};
            mma16(c1[nt], ah, bh);   // hi*hi
            mma16(c2[nt], ah, bl);   // hi*lo
            mma16(c1[nt], al, bh);   // lo*hi
        }
    }
#pragma unroll
    for (int nt = 0; nt < NT; nt++)
#pragma unroll
        for (int i = 0; i < 4; i++) out[nt][i] = c1[nt][i] + c2[nt][i];
}

// write packed pair (uint2) for k-pair kp of row b into a [row][ks][q] uint4 array
DEV_INLINE void store_pk(uint4* arr, int b, int kp, uint32_t hi, uint32_t lo) {
    int ks = kp >> 3, q = kp & 3, half = (kp >> 2) & 1;
    uint2* p = reinterpret_cast<uint2*>(arr + ((size_t)b * kKS + ks) * 4 + q) + half;
    *p = make_uint2(hi, lo);
}

// ---------------- persistent recurrence kernel -------------------------------
// 128 CTAs = 64 col-groups (cg) x 2 row-groups (rg, 32 rows each).
// 512 threads = 2 m-warps (mq) x 8 k-warps (kq, 8 ks-chunks each).
// Phase A: cg<32 -> z cols 32cg..32cg+31; cg>=32 -> r cols (NT=4).
// Phase B: s cols 16cg..16cg+15 (NT=2). Two-round cross-K reduction in smem.

__global__ void __launch_bounds__(512, 1) recur_kernel() {
    extern __shared__ uint4 smem[];
    uint4* smemA = smem;                       // 32 cols, stride CPA
    uint4* smemB = smem + kSmemA4;             // 16 cols, stride CPB
    float* red   = reinterpret_cast<float*>(smem + kSmemA4 + kSmemB4);

    const int c    = blockIdx.x;
    const int cg   = c & 63, rg = c >> 6;
    const int rb   = rg * 32;                  // CTA row base
    const int tid  = threadIdx.x;
    const int wid  = tid >> 5, lane = tid & 31;
    const int mq   = wid & 1, kq = wid >> 1;   // kq in 0..7
    const int wm   = rb + mq * 16;
    const int ks0  = kq * 8;
    const int grp  = lane >> 2, tg = lane & 3;

    const int gate = (cg >= 32) ? 1 : 0;
    const int jA   = (cg & 31) * 32;
    const int jB   = cg * 16;

    // ---- prolog: load this CTA's weight slices into smem (once) ----
    {
        const uint2* __restrict__ wa = g_wpk + ((size_t)gate * kDh + jA) * kKP;
        for (int idx = tid; idx < 32 * kKP; idx += 512) {
            int j = idx >> 9, kp = idx & (kKP - 1);
            uint2 v = wa[(size_t)j * kKP + kp];
            int ks = kp >> 3, q = kp & 3, half = (kp >> 2) & 1;
            uint2* p = reinterpret_cast<uint2*>(&smemA[(ks * 4 + q) * CPA + j]) + half;
            *p = v;
        }
        const uint2* __restrict__ wb = g_wpk + ((size_t)2 * kDh + jB) * kKP;
        for (int idx = tid; idx < 16 * kKP; idx += 512) {
            int j = idx >> 9, kp = idx & (kKP - 1);
            uint2 v = wb[(size_t)j * kKP + kp];
            int ks = kp >> 3, q = kp & 3, half = (kp >> 2) & 1;
            uint2* p = reinterpret_cast<uint2*>(&smemB[(ks * 4 + q) * CPB + j]) + half;
            *p = v;
        }
        __syncthreads();
    }

    for (int t = 0; t < kT; ++t) {
        // ---------- phase A: z (cg<32) or r (cg>=32) over rows rb..rb+31 ------
        {
            float acc[4][4];
            gemm8<4, CPA>(g_hpk4, smemA, ks0, wm + grp, wm + grp + 8, grp, tg, acc);

            const float* __restrict__ xg = g_xbuf + ((size_t)t * 3 + gate) * kB * kDh;
            const float* __restrict__ hp = g_hs + (size_t)t * kB * kDh;
            float2 xv[4][2], hv[4][2];
            if (kq == 0) {
#pragma unroll
                for (int nt = 0; nt < 4; nt++)
#pragma unroll
                    for (int half = 0; half < 2; half++) {
                        const int b = wm + grp + half * 8;
                        const int j = jA + nt * 8 + 2 * tg;
                        xv[nt][half] = *reinterpret_cast<const float2*>(xg + (size_t)b * kDh + j);
                        if (gate)
                            hv[nt][half] = *reinterpret_cast<const float2*>(hp + (size_t)b * kDh + j);
                    }
            }

            // two-round reduction: 8 partials -> 1 (4-layer buffer)
            if (kq >= 4) {
#pragma unroll
                for (int nt = 0; nt < 4; nt++)
#pragma unroll
                    for (int i = 0; i < 4; i++)
                        red[((kq - 4) * 32 + mq * 16 + nt * 4 + i) * 32 + lane] = acc[nt][i];
            }
            __syncthreads();
            if (kq < 4) {
#pragma unroll
                for (int nt = 0; nt < 4; nt++)
#pragma unroll
                    for (int i = 0; i < 4; i++)
                        acc[nt][i] += red[(kq * 32 + mq * 16 + nt * 4 + i) * 32 + lane];
            }
            __syncthreads();
            if (kq >= 1 && kq < 4) {
#pragma unroll
                for (int nt = 0; nt < 4; nt++)
#pragma unroll
                    for (int i = 0; i < 4; i++)
                        red[((kq - 1) * 32 + mq * 16 + nt * 4 + i) * 32 + lane] = acc[nt][i];
            }
            __syncthreads();
            if (kq == 0) {
#pragma unroll
                for (int nt = 0; nt < 4; nt++)
#pragma unroll
                    for (int i = 0; i < 4; i++) {
                        const int r = (mq * 16 + nt * 4 + i) * 32 + lane;
                        acc[nt][i] += red[r] + red[32 * 32 + r] + red[2 * 32 * 32 + r];
                    }
#pragma unroll
                for (int nt = 0; nt < 4; nt++)
#pragma unroll
                    for (int half = 0; half < 2; half++) {
                        const int b = wm + grp + half * 8;
                        const int j = jA + nt * 8 + 2 * tg;
                        const float g0 = sigmoidf_(acc[nt][2 * half + 0] + xv[nt][half].x);
                        const float g1 = sigmoidf_(acc[nt][2 * half + 1] + xv[nt][half].y);
                        if (gate == 0) {
                            *reinterpret_cast<float2*>(g_z + (size_t)b * kDh + j) =
                                make_float2(g0, g1);
                        } else {
                            uint32_t hi, lo;
                            split2(g0 * hv[nt][half].x, g1 * hv[nt][half].y, hi, lo);
                            store_pk(g_rhpk4, b, j >> 1, hi, lo);
                        }
                    }
            }
        }
        grid_barrier(c, 2 * t + 1);

        // ---------- phase B: s gate + h update over rows rb..rb+31 ------------
        {
            float acc[2][4];
            gemm8<2, CPB>(g_rhpk4, smemB, ks0, wm + grp, wm + grp + 8, grp, tg, acc);

            const float* __restrict__ xs = g_xbuf + ((size_t)t * 3 + 2) * kB * kDh;
            const float* __restrict__ hp = g_hs + (size_t)t * kB * kDh;
            float* __restrict__ hn       = g_hs + (size_t)(t + 1) * kB * kDh;
            float2 xv[2][2], hv[2][2], zv[2][2];
            if (kq == 0) {
#pragma unroll
                for (int nt = 0; nt < 2; nt++)
#pragma unroll
                    for (int half = 0; half < 2; half++) {
                        const int b = wm + grp + half * 8;
                        const int j = jB + nt * 8 + 2 * tg;
                        const size_t o = (size_t)b * kDh + j;
                        xv[nt][half] = *reinterpret_cast<const float2*>(xs + o);
                        hv[nt][half] = *reinterpret_cast<const float2*>(hp + o);
                        zv[nt][half] = *reinterpret_cast<const float2*>(g_z + o);
                    }
            }

            if (kq >= 4) {
#pragma unroll
                for (int nt = 0; nt < 2; nt++)
#pragma unroll
                    for (int i = 0; i < 4; i++)
                        red[((kq - 4) * 32 + mq * 8 + nt * 4 + i) * 32 + lane] = acc[nt][i];
            }
            __syncthreads();
            if (kq < 4) {
#pragma unroll
                for (int nt = 0; nt < 2; nt++)
#pragma unroll
                    for (int i = 0; i < 4; i++)
                        acc[nt][i] += red[(kq * 32 + mq * 8 + nt * 4 + i) * 32 + lane];
            }
            __syncthreads();
            if (kq >= 1 && kq < 4) {
#pragma unroll
                for (int nt = 0; nt < 2; nt++)
#pragma unroll
                    for (int i = 0; i < 4; i++)
                        red[((kq - 1) * 32 + mq * 8 + nt * 4 + i) * 32 + lane] = acc[nt][i];
            }
            __syncthreads();
            if (kq == 0) {
#pragma unroll
                for (int nt = 0; nt < 2; nt++)
#pragma unroll
                    for (int i = 0; i < 4; i++) {
                        const int r = (mq * 8 + nt * 4 + i) * 32 + lane;
                        acc[nt][i] += red[r] + red[32 * 32 + r] + red[2 * 32 * 32 + r];
                    }
#pragma unroll
                for (int nt = 0; nt < 2; nt++)
#pragma unroll
                    for (int half = 0; half < 2; half++) {
                        const int b = wm + grp + half * 8;
                        const int j = jB + nt * 8 + 2 * tg;
                        const size_t o = (size_t)b * kDh + j;
                        const float st0 = tanhf(acc[nt][2 * half + 0] + xv[nt][half].x);
                        const float st1 = tanhf(acc[nt][2 * half + 1] + xv[nt][half].y);
                        const float h0 = hv[nt][half].x, h1 = hv[nt][half].y;
                        const float v0 = fmaf(zv[nt][half].x, st0 - h0, h0);
                        const float v1 = fmaf(zv[nt][half].y, st1 - h1, h1);
                        *reinterpret_cast<float2*>(hn + o) = make_float2(v0, v1);
                        uint32_t hi, lo;
                        split2(v0, v1, hi, lo);
                        store_pk(g_hpk4, b, j >> 1, hi, lo);
                        g_hspk[((size_t)t * kB + b) * kKP + (j >> 1)] = make_uint2(hi, lo);
                    }
            }
        }
        grid_barrier(c, 2 * t + 2);
    }
}

// ---------------- output projection: relu(hs @ Wo + bo), packed operands -----

__global__ void out_proj_kernel(const float* __restrict__ bo,
                                float* __restrict__ out) {
    const int t  = blockIdx.x;
    const int c0 = blockIdx.y * 64;

    __shared__ uint32_t Ah[64][17], Al[64][17];
    __shared__ uint32_t Bh[64][17], Bl[64][17];

    const int tid = threadIdx.x;
    const int wid = tid >> 5, lane = tid & 31;
    const int wm  = (wid & 3) * 16;
    const int wn  = (wid >> 2) * 32;
    const int grp = lane >> 2, tg = lane & 3;

    const uint2* __restrict__ Apk = g_hspk + (size_t)t * kB * kKP;

    float acc[4][4] = {};

    for (int kp0 = 0; kp0 < kKP; kp0 += 16) {
        for (int idx = tid; idx < 64 * 16; idx += 256) {
            int kp = idx & 15, m = idx >> 4;
            uint2 v = Apk[(size_t)m * kKP + kp0 + kp];
            Ah[m][kp] = v.x; Al[m][kp] = v.y;
        }
        for (int idx = tid; idx < 64 * 16; idx += 256) {
            int kp = idx & 15, j = idx >> 4;
            uint2 v = g_wopk[(size_t)(c0 + j) * kKP + kp0 + kp];
            Bh[j][kp] = v.x; Bl[j][kp] = v.y;
        }
        __syncthreads();
#pragma unroll
        for (int kt = 0; kt < 2; kt++) {
            uint32_t ah[4], al[4];
            ah[0] = Ah[wm + grp][kt * 8 + tg];         al[0] = Al[wm + grp][kt * 8 + tg];
            ah[1] = Ah[wm + grp + 8][kt * 8 + tg];     al[1] = Al[wm + grp + 8][kt * 8 + tg];
            ah[2] = Ah[wm + grp][kt * 8 + tg + 4];     al[2] = Al[wm + grp][kt * 8 + tg + 4];
            ah[3] = Ah[wm + grp + 8][kt * 8 + tg + 4]; al[3] = Al[wm + grp + 8][kt * 8 + tg + 4];
#pragma unroll
            for (int nt = 0; nt < 4; nt++) {
                const int jj = wn + nt * 8 + grp;
                uint32_t bh[2], bl[2];
                bh[0] = Bh[jj][kt * 8 + tg];     bl[0] = Bl[jj][kt * 8 + tg];
                bh[1] = Bh[jj][kt * 8 + tg + 4]; bl[1] = Bl[jj][kt * 8 + tg + 4];
                mma16(acc[nt], ah, bh);
                mma16(acc[nt], ah, bl);
                mma16(acc[nt], al, bh);
            }
        }
        __syncthreads();
    }

#pragma unroll
    for (int nt = 0; nt < 4; nt++) {
#pragma unroll
        for (int cc = 0; cc < 4; cc++) {
            int b   = wm + grp + ((cc & 2) ? 8 : 0);
            int col = c0 + wn + nt * 8 + 2 * tg + (cc & 1);
            float v = acc[nt][cc] + bo[col];
            out[((size_t)b * kT + t) * kDout + col] = fmaxf(v, 0.0f);
        }
    }
}

// ---------------- h_final copy ----------------------------------------------

__global__ void final_copy_kernel(float* __restrict__ out) {
    int i = blockIdx.x * blockDim.x + threadIdx.x;
    if (i < kB * kDh)
        out[(size_t)kB * kT * kDout + i] = g_hs[(size_t)kT * kB * kDh + i];
}

// ---------------- launch ------------------------------------------------------
// d_in: inputs, Wz, bz, Wr, br, Ws, bs, Wo, bo ; d_out: [outputs | h_final] fp32

extern "C" void kernel_launch(void* const* d_in, const int* in_sizes, int n_in,
                              void* d_out, int out_size) {
    (void)in_sizes; (void)n_in; (void)out_size;
    const float* inp = (const float*)d_in[0];
    const float* Wz  = (const float*)d_in[1];
    const float* bz  = (const float*)d_in[2];
    const float* Wr  = (const float*)d_in[3];
    const float* br  = (const float*)d_in[4];
    const float* Ws  = (const float*)d_in[5];
    const float* bs  = (const float*)d_in[6];
    const float* Wo  = (const float*)d_in[7];
    const float* bo  = (const float*)d_in[8];
    float* out = (float*)d_out;

    cudaFuncSetAttribute(recur_kernel, cudaFuncAttributeMaxDynamicSharedMemorySize,
                         (int)kSmemBytes);

    zero_h0_kernel<<<(kB * kDh + 255) / 256, 256>>>();
    prep_w_kernel<<<(3 * kKP * kDh + 255) / 256, 256>>>(Wz, Wr, Ws);
    prep_wx_kernel<<<(3 * kDh * kKPx + 255) / 256, 256>>>(Wz, Wr, Ws);
    prep_wo_kernel<<<(kDout * kKP + 255) / 256, 256>>>(Wo);
    prep_in_kernel<<<(kB * kT * kKPx + 255) / 256, 256>>>(inp);
    proj_x_kernel<<<dim3(kB * kT / 64, 3 * kDh / 64), 256>>>(bz, br, bs);
    recur_kernel<<<kNC, 512, kSmemBytes>>>();
    out_proj_kernel<<<dim3(kT, kDout / 64), 256>>>(bo, out);
    final_copy_kernel<<<(kB * kDh + 255) / 256, 256>>>(out);
}

// round 17
// speedup vs baseline: 1.0883x; 1.0883x over previous
#include <cuda_runtime.h>
#include <cuda_bf16.h>
#include <cstdint>
#include <cstddef>

#define DEV_INLINE __device__ __forceinline__

namespace {
constexpr int kB    = 64;
constexpr int kT    = 512;
constexpr int kDin  = 512;
constexpr int kDh   = 1024;
constexpr int kDout = 1024;
constexpr int kNC   = 128;       // persistent CTA count
constexpr int kKP   = kDh / 2;   // 512 k-pairs (recurrent K)
constexpr int kKPx  = kDin / 2;  // 256 k-pairs (input K)
constexpr int kKS   = kKP / 8;   // 64 k-chunks
constexpr int CPA   = 17;        // padded col stride, phase A smem B (16 cols)
constexpr int CPB   = 9;         // padded col stride, phase B smem B (8 cols)
constexpr int kSmemA4 = kKS * 4 * CPA;
constexpr int kSmemB4 = kKS * 4 * CPB;
constexpr int kRedFloats = 4 * 64 * 32;             // 4 partial layers (32 KB)
constexpr size_t kSmemBytes = (size_t)(kSmemA4 + kSmemB4) * 16 + kRedFloats * 4;
}

// ---------------- device scratch (no allocs allowed) ------------------------
__device__ float g_xbuf[(size_t)kT * 3 * kB * kDh];   // [t][gate][b][j]
__device__ float g_hs[(size_t)(kT + 1) * kB * kDh];   // [t][b][j]
__device__ float g_z[(size_t)kB * kDh];
__device__ uint4 g_hpk4[(size_t)kB * kKS * 4];
__device__ uint4 g_rhpk4[(size_t)kB * kKS * 4];
__device__ uint2 g_wpk[(size_t)3 * kDh * kKP];
__device__ uint2 g_inpk[(size_t)kB * kT * kKPx];
__device__ uint2 g_wxpk[(size_t)3 * kDh * kKPx];
__device__ uint2 g_wopk[(size_t)kDout * kKP];
__device__ uint2 g_hspk[(size_t)kT * kB * kKP];
__device__ unsigned g_bar_cnt = 0;
__device__ unsigned g_bar_gen = 0;

// ---------------- bf16 split helpers ----------------------------------------

DEV_INLINE void split2(float x0, float x1, uint32_t& hi, uint32_t& lo) {
    __nv_bfloat16 h0 = __float2bfloat16_rn(x0);
    __nv_bfloat16 h1 = __float2bfloat16_rn(x1);
    __nv_bfloat16 l0 = __float2bfloat16_rn(x0 - __bfloat162float(h0));
    __nv_bfloat16 l1 = __float2bfloat16_rn(x1 - __bfloat162float(h1));
    hi = (uint32_t)__bfloat16_as_ushort(h0) | ((uint32_t)__bfloat16_as_ushort(h1) << 16);
    lo = (uint32_t)__bfloat16_as_ushort(l0) | ((uint32_t)__bfloat16_as_ushort(l1) << 16);
}

DEV_INLINE void mma16(float c[4], const uint32_t a[4], const uint32_t b[2]) {
    asm volatile(
        "mma.sync.aligned.m16n8k16.row.col.f32.bf16.bf16.f32 "
        "{%0,%1,%2,%3}, {%4,%5,%6,%7}, {%8,%9}, {%0,%1,%2,%3};\n"
        : "+f"(c[0]), "+f"(c[1]), "+f"(c[2]), "+f"(c[3])
        : "r"(a[0]), "r"(a[1]), "r"(a[2]), "r"(a[3]), "r"(b[0]), "r"(b[1]));
}

DEV_INLINE float sigmoidf_(float x) { return 1.0f / (1.0f + __expf(-x)); }

// ---------------- init -------------------------------------------------------

__global__ void zero_h0_kernel() {
    int i = blockIdx.x * blockDim.x + threadIdx.x;
    if (i < kB * kDh) g_hs[i] = 0.0f;
    if (i < kB * kKS * 4) g_hpk4[i] = make_uint4(0u, 0u, 0u, 0u);
}

// ---------------- packers ----------------------------------------------------

__global__ void prep_w_kernel(const float* __restrict__ Wz,
                              const float* __restrict__ Wr,
                              const float* __restrict__ Ws) {
    size_t i = (size_t)blockIdx.x * blockDim.x + threadIdx.x;
    if (i >= (size_t)3 * kKP * kDh) return;
    int j  = (int)(i & (kDh - 1));
    int kp = (int)((i >> 10) & (kKP - 1));
    int g  = (int)(i >> 19);
    const float* W = (g == 0) ? Wz : (g == 1) ? Wr : Ws;
    uint32_t hi, lo;
    split2(W[(size_t)(2 * kp) * kDh + j], W[(size_t)(2 * kp + 1) * kDh + j], hi, lo);
    g_wpk[((size_t)g * kDh + j) * kKP + kp] = make_uint2(hi, lo);
}

__global__ void prep_wx_kernel(const float* __restrict__ Wz,
                               const float* __restrict__ Wr,
                               const float* __restrict__ Ws) {
    size_t i = (size_t)blockIdx.x * blockDim.x + threadIdx.x;
    if (i >= (size_t)3 * kDh * kKPx) return;
    int kp = (int)(i & (kKPx - 1));
    int j  = (int)((i >> 8) & (kDh - 1));
    int g  = (int)(i >> 18);
    const float* W = (g == 0) ? Wz : (g == 1) ? Wr : Ws;
    uint32_t hi, lo;
    split2(W[(size_t)(kDh + 2 * kp) * kDh + j],
           W[(size_t)(kDh + 2 * kp + 1) * kDh + j], hi, lo);
    g_wxpk[((size_t)g * kDh + j) * kKPx + kp] = make_uint2(hi, lo);
}

__global__ void prep_wo_kernel(const float* __restrict__ Wo) {
    size_t i = (size_t)blockIdx.x * blockDim.x + threadIdx.x;
    if (i >= (size_t)kDout * kKP) return;
    int kp = (int)(i & (kKP - 1));
    int o  = (int)(i >> 9);
    uint32_t hi, lo;
    split2(Wo[(size_t)(2 * kp) * kDout + o], Wo[(size_t)(2 * kp + 1) * kDout + o], hi, lo);
    g_wopk[(size_t)o * kKP + kp] = make_uint2(hi, lo);
}

__global__ void prep_in_kernel(const float* __restrict__ inp) {
    size_t i = (size_t)blockIdx.x * blockDim.x + threadIdx.x;
    if (i >= (size_t)kB * kT * kKPx) return;
    const float2 v = *reinterpret_cast<const float2*>(inp + 2 * i);
    uint32_t hi, lo;
    split2(v.x, v.y, hi, lo);
    g_inpk[i] = make_uint2(hi, lo);
}

// ---------------- x-projections (packed operands, legacy mma) ----------------

__global__ void proj_x_kernel(const float* __restrict__ bz,
                              const float* __restrict__ br,
                              const float* __restrict__ bs) {
    const int r0   = blockIdx.x * 64;
    const int c0   = blockIdx.y * 64;
    const int gate = c0 >> 10;
    const int jg0  = c0 & (kDh - 1);
    const float* __restrict__ bias = (gate == 0) ? bz : (gate == 1) ? br : bs;

    __shared__ uint32_t Ah[64][17], Al[64][17];
    __shared__ uint32_t Bh[64][17], Bl[64][17];

    const int tid = threadIdx.x;
    const int wid = tid >> 5, lane = tid & 31;
    const int wm  = (wid & 3) * 16;
    const int wn  = (wid >> 2) * 32;
    const int grp = lane >> 2, tg = lane & 3;

    const uint2* __restrict__ Bw = g_wxpk + (size_t)gate * kDh * kKPx;

    float acc[4][4] = {};

    for (int kp0 = 0; kp0 < kKPx; kp0 += 16) {
        for (int idx = tid; idx < 64 * 16; idx += 256) {
            int kp = idx & 15, m = idx >> 4;
            uint2 v = g_inpk[(size_t)(r0 + m) * kKPx + kp0 + kp];
            Ah[m][kp] = v.x; Al[m][kp] = v.y;
        }
        for (int idx = tid; idx < 64 * 16; idx += 256) {
            int kp = idx & 15, j = idx >> 4;
            uint2 v = Bw[(size_t)(jg0 + j) * kKPx + kp0 + kp];
            Bh[j][kp] = v.x; Bl[j][kp] = v.y;
        }
        __syncthreads();
#pragma unroll
        for (int kt = 0; kt < 2; kt++) {
            uint32_t ah[4], al[4];
            ah[0] = Ah[wm + grp][kt * 8 + tg];         al[0] = Al[wm + grp][kt * 8 + tg];
            ah[1] = Ah[wm + grp + 8][kt * 8 + tg];     al[1] = Al[wm + grp + 8][kt * 8 + tg];
            ah[2] = Ah[wm + grp][kt * 8 + tg + 4];     al[2] = Al[wm + grp][kt * 8 + tg + 4];
            ah[3] = Ah[wm + grp + 8][kt * 8 + tg + 4]; al[3] = Al[wm + grp + 8][kt * 8 + tg + 4];
#pragma unroll
            for (int nt = 0; nt < 4; nt++) {
                const int jj = wn + nt * 8 + grp;
                uint32_t bh[2], bl[2];
                bh[0] = Bh[jj][kt * 8 + tg];     bl[0] = Bl[jj][kt * 8 + tg];
                bh[1] = Bh[jj][kt * 8 + tg + 4]; bl[1] = Bl[jj][kt * 8 + tg + 4];
                mma16(acc[nt], ah, bh);
                mma16(acc[nt], ah, bl);
                mma16(acc[nt], al, bh);
            }
        }
        __syncthreads();
    }

#pragma unroll
    for (int nt = 0; nt < 4; nt++) {
#pragma unroll
        for (int cc = 0; cc < 4; cc++) {
            int row = r0 + wm + grp + ((cc & 2) ? 8 : 0);
            int col = jg0 + wn + nt * 8 + 2 * tg + (cc & 1);
            int b = row >> 9;
            int t = row & (kT - 1);
            g_xbuf[(((size_t)t * 3 + gate) * kB + b) * kDh + col] = acc[nt][cc] + bias[col];
        }
    }
}

// ---------------- fast grid barrier ------------------------------------------

DEV_INLINE void grid_barrier() {
    __syncthreads();
    if (threadIdx.x == 0) {
        unsigned gen;
        asm volatile("ld.acquire.gpu.global.u32 %0, [%1];" : "=r"(gen) : "l"(&g_bar_gen));
        unsigned old;
        asm volatile("atom.release.gpu.global.add.u32 %0, [%1], 1;" : "=r"(old) : "l"(&g_bar_cnt));
        if (old == kNC - 1u) {
            asm volatile("st.relaxed.gpu.global.u32 [%0], 0;" :: "l"(&g_bar_cnt));
            asm volatile("st.release.gpu.global.u32 [%0], %1;" :: "l"(&g_bar_gen), "r"(gen + 1u));
        } else {
            unsigned cur;
            do {
                asm volatile("ld.acquire.gpu.global.u32 %0, [%1];" : "=r"(cur) : "l"(&g_bar_gen));
            } while (cur == gen);
        }
    }
    __syncthreads();
}

// ---------------- GEMM core: warp m16 x (NT*8), 16 k-chunks, B from smem -----

template <int NT, int CPAD>
DEV_INLINE void gemm_smem(const uint4* __restrict__ A4, const uint4* __restrict__ Bs,
                          int ks0, int wm, int grp, int tg, float out[NT][4]) {
    const uint4* __restrict__ r0p = A4 + (size_t)(wm + grp) * (kKS * 4) + tg;
    const uint4* __restrict__ r1p = A4 + (size_t)(wm + grp + 8) * (kKS * 4) + tg;

    float hh[NT][4], hl[NT][4], lh[NT][4];
#pragma unroll
    for (int nt = 0; nt < NT; nt++)
#pragma unroll
        for (int i = 0; i < 4; i++) { hh[nt][i] = 0.f; hl[nt][i] = 0.f; lh[nt][i] = 0.f; }

    uint4 abuf[2][2];
    abuf[0][0] = r0p[ks0 * 4];        abuf[0][1] = r1p[ks0 * 4];
    abuf[1][0] = r0p[(ks0 + 1) * 4];  abuf[1][1] = r1p[(ks0 + 1) * 4];

#pragma unroll 4
    for (int s = 0; s < 16; s++) {
        const int ks = ks0 + s;
        const uint4 a0 = abuf[s & 1][0];
        const uint4 a1 = abuf[s & 1][1];
        if (s + 2 < 16) {
            abuf[s & 1][0] = r0p[(ks + 2) * 4];
            abuf[s & 1][1] = r1p[(ks + 2) * 4];
        }
        uint4 bq[NT];
        const uint4* __restrict__ brow = Bs + (ks * 4 + tg) * CPAD + grp;
#pragma unroll
        for (int nt = 0; nt < NT; nt++) bq[nt] = brow[nt * 8];

        const uint32_t ah[4] = {a0.x, a1.x, a0.z, a1.z};
        const uint32_t al[4] = {a0.y, a1.y, a0.w, a1.w};
#pragma unroll
        for (int nt = 0; nt < NT; nt++) {
            const uint32_t bh[2] = {bq[nt].x, bq[nt].z};
            const uint32_t bl[2] = {bq[nt].y, bq[nt].w};
            mma16(hh[nt], ah, bh);
            mma16(hl[nt], ah, bl);
            mma16(lh[nt], al, bh);
        }
    }
#pragma unroll
    for (int nt = 0; nt < NT; nt++)
#pragma unroll
        for (int i = 0; i < 4; i++) out[nt][i] = hh[nt][i] + hl[nt][i] + lh[nt][i];
}

DEV_INLINE void store_pk(uint4* arr, int b, int kp, uint32_t hi, uint32_t lo) {
    int ks = kp >> 3, q = kp & 3, half = (kp >> 2) & 1;
    uint2* p = reinterpret_cast<uint2*>(arr + ((size_t)b * kKS + ks) * 4 + q) + half;
    *p = make_uint2(hi, lo);
}

// ---------------- persistent recurrence kernel -------------------------------
// 128 CTAs x 512 threads = 4 m-warps x 4 kq-warps (R12 gemm layout).
// NEW: all warps write partials to smem; distributed per-thread epilogue.

__global__ void __launch_bounds__(512, 1) recur_kernel() {
    extern __shared__ uint4 rsmem[];
    uint4* smemA = rsmem;
    uint4* smemB = rsmem + kSmemA4;
    float* red   = reinterpret_cast<float*>(rsmem + kSmemA4 + kSmemB4);

    const int c    = blockIdx.x;
    const int tid  = threadIdx.x;
    const int wid  = tid >> 5, lane = tid & 31;
    const int mq   = wid & 3, kq = wid >> 2;
    const int wm   = mq * 16;
    const int ks0  = kq * 16;
    const int grp  = lane >> 2, tg = lane & 3;

    const int gate = (c >= 64) ? 1 : 0;
    const int jA   = (c & 63) * 16;
    const int jB   = c * 8;

    // epilogue ownership: phase A pair (eb, jA + 2*ejp); phase B (bb, jB + 2*bjp)
    const int eb  = tid >> 3, ejp = tid & 7;
    const int ebase = ((eb >> 4) * 16 + (ejp >> 2) * 4 + 2 * ((eb >> 3) & 1)) * 32
                      + (eb & 7) * 4 + (ejp & 3);
    const size_t eo = (size_t)eb * kDh + jA + 2 * ejp;
    const int bb  = (tid & 255) >> 2, bjp = tid & 3;
    const int bbase = ((bb >> 4) * 16 + 2 * ((bb >> 3) & 1)) * 32 + (bb & 7) * 4 + bjp;
    const size_t bo = (size_t)bb * kDh + jB + 2 * bjp;

    // ---- prolog: load this CTA's weight slices into smem (once) ----
    {
        const uint2* __restrict__ wa = g_wpk + ((size_t)gate * kDh + jA) * kKP;
        for (int idx = tid; idx < 16 * kKP; idx += 512) {
            int j = idx >> 9, kp = idx & (kKP - 1);
            uint2 v = wa[(size_t)j * kKP + kp];
            int ks = kp >> 3, q = kp & 3, half = (kp >> 2) & 1;
            uint2* p = reinterpret_cast<uint2*>(&smemA[(ks * 4 + q) * CPA + j]) + half;
            *p = v;
        }
        const uint2* __restrict__ wb = g_wpk + ((size_t)2 * kDh + jB) * kKP;
        for (int idx = tid; idx < 8 * kKP; idx += 512) {
            int j = idx >> 9, kp = idx & (kKP - 1);
            uint2 v = wb[(size_t)j * kKP + kp];
            int ks = kp >> 3, q = kp & 3, half = (kp >> 2) & 1;
            uint2* p = reinterpret_cast<uint2*>(&smemB[(ks * 4 + q) * CPB + j]) + half;
            *p = v;
        }
        __syncthreads();
    }

    for (int t = 0; t < kT; ++t) {
        // ---------- phase A: z (c<64) or r (c>=64) ----------
        {
            const float* __restrict__ xg = g_xbuf + ((size_t)t * 3 + gate) * kB * kDh;
            const float* __restrict__ hp = g_hs + (size_t)t * kB * kDh;

            // hoisted per-thread epilogue operands
            const float2 exv = *reinterpret_cast<const float2*>(xg + eo);
            float2 ehv = make_float2(0.f, 0.f);
            if (gate) ehv = *reinterpret_cast<const float2*>(hp + eo);

            float acc[2][4];
            gemm_smem<2, CPA>(g_hpk4, smemA, ks0, wm, grp, tg, acc);

            // all warps write partials (layer = kq)
#pragma unroll
            for (int nt = 0; nt < 2; nt++)
#pragma unroll
                for (int i = 0; i < 4; i++)
                    red[kq * 2048 + (mq * 16 + nt * 4 + i) * 32 + lane] = acc[nt][i];
            __syncthreads();

            // distributed epilogue: one (j, j+1) pair per thread
            {
                const float v0 = red[ebase] + red[2048 + ebase] +
                                 red[4096 + ebase] + red[6144 + ebase];
                const float v1 = red[ebase + 32] + red[2048 + ebase + 32] +
                                 red[4096 + ebase + 32] + red[6144 + ebase + 32];
                const float g0 = sigmoidf_(v0 + exv.x);
                const float g1 = sigmoidf_(v1 + exv.y);
                if (gate == 0) {
                    *reinterpret_cast<float2*>(g_z + eo) = make_float2(g0, g1);
                } else {
                    uint32_t hi, lo;
                    split2(g0 * ehv.x, g1 * ehv.y, hi, lo);
                    store_pk(g_rhpk4, eb, (jA >> 1) + ejp, hi, lo);
                }
            }
        }
        grid_barrier();

        // ---------- phase B: s gate + h update ----------
        {
            const float* __restrict__ xs = g_xbuf + ((size_t)t * 3 + 2) * kB * kDh;
            const float* __restrict__ hp = g_hs + (size_t)t * kB * kDh;
            float* __restrict__ hn       = g_hs + (size_t)(t + 1) * kB * kDh;

            float2 bxv = make_float2(0.f, 0.f), bhv = bxv, bzv = bxv;
            if (tid < 256) {
                bxv = *reinterpret_cast<const float2*>(xs + bo);
                bhv = *reinterpret_cast<const float2*>(hp + bo);
                bzv = *reinterpret_cast<const float2*>(g_z + bo);
            }

            float acc[1][4];
            gemm_smem<1, CPB>(g_rhpk4, smemB, ks0, wm, grp, tg, acc);

#pragma unroll
            for (int i = 0; i < 4; i++)
                red[kq * 2048 + (mq * 16 + i) * 32 + lane] = acc[0][i];
            __syncthreads();

            if (tid < 256) {
                const float v0 = red[bbase] + red[2048 + bbase] +
                                 red[4096 + bbase] + red[6144 + bbase];
                const float v1 = red[bbase + 32] + red[2048 + bbase + 32] +
                                 red[4096 + bbase + 32] + red[6144 + bbase + 32];
                const float st0 = tanhf(v0 + bxv.x);
                const float st1 = tanhf(v1 + bxv.y);
                const float h0 = bhv.x, h1 = bhv.y;
                const float n0 = fmaf(bzv.x, st0 - h0, h0);
                const float n1 = fmaf(bzv.y, st1 - h1, h1);
                *reinterpret_cast<float2*>(hn + bo) = make_float2(n0, n1);
                uint32_t hi, lo;
                split2(n0, n1, hi, lo);
                store_pk(g_hpk4, bb, (jB >> 1) + bjp, hi, lo);
                g_hspk[((size_t)t * kB + bb) * kKP + (jB >> 1) + bjp] = make_uint2(hi, lo);
            }
        }
        grid_barrier();
    }
}

// ---------------- output projection (legacy mma, packed) ----------------------

__global__ void out_proj_kernel(const float* __restrict__ bo,
                                float* __restrict__ out) {
    const int t  = blockIdx.x;
    const int c0 = blockIdx.y * 64;

    __shared__ uint32_t Ah[64][17], Al[64][17];
    __shared__ uint32_t Bh[64][17], Bl[64][17];

    const int tid = threadIdx.x;
    const int wid = tid >> 5, lane = tid & 31;
    const int wm  = (wid & 3) * 16;
    const int wn  = (wid >> 2) * 32;
    const int grp = lane >> 2, tg = lane & 3;

    const uint2* __restrict__ Apk = g_hspk + (size_t)t * kB * kKP;

    float acc[4][4] = {};

    for (int kp0 = 0; kp0 < kKP; kp0 += 16) {
        for (int idx = tid; idx < 64 * 16; idx += 256) {
            int kp = idx & 15, m = idx >> 4;
            uint2 v = Apk[(size_t)m * kKP + kp0 + kp];
            Ah[m][kp] = v.x; Al[m][kp] = v.y;
        }
        for (int idx = tid; idx < 64 * 16; idx += 256) {
            int kp = idx & 15, j = idx >> 4;
            uint2 v = g_wopk[(size_t)(c0 + j) * kKP + kp0 + kp];
            Bh[j][kp] = v.x; Bl[j][kp] = v.y;
        }
        __syncthreads();
#pragma unroll
        for (int kt = 0; kt < 2; kt++) {
            uint32_t ah[4], al[4];
            ah[0] = Ah[wm + grp][kt * 8 + tg];         al[0] = Al[wm + grp][kt * 8 + tg];
            ah[1] = Ah[wm + grp + 8][kt * 8 + tg];     al[1] = Al[wm + grp + 8][kt * 8 + tg];
            ah[2] = Ah[wm + grp][kt * 8 + tg + 4];     al[2] = Al[wm + grp][kt * 8 + tg + 4];
            ah[3] = Ah[wm + grp + 8][kt * 8 + tg + 4]; al[3] = Al[wm + grp + 8][kt * 8 + tg + 4];
#pragma unroll
            for (int nt = 0; nt < 4; nt++) {
                const int jj = wn + nt * 8 + grp;
                uint32_t bh[2], bl[2];
                bh[0] = Bh[jj][kt * 8 + tg];     bl[0] = Bl[jj][kt * 8 + tg];
                bh[1] = Bh[jj][kt * 8 + tg + 4]; bl[1] = Bl[jj][kt * 8 + tg + 4];
                mma16(acc[nt], ah, bh);
                mma16(acc[nt], ah, bl);
                mma16(acc[nt], al, bh);
            }
        }
        __syncthreads();
    }

#pragma unroll
    for (int nt = 0; nt < 4; nt++) {
#pragma unroll
        for (int cc = 0; cc < 4; cc++) {
            int b   = wm + grp + ((cc & 2) ? 8 : 0);
            int col = c0 + wn + nt * 8 + 2 * tg + (cc & 1);
            float v = acc[nt][cc] + bo[col];
            out[((size_t)b * kT + t) * kDout + col] = fmaxf(v, 0.0f);
        }
    }
}

// ---------------- h_final copy ------------------------------------------------

__global__ void final_copy_kernel(float* __restrict__ out) {
    int i = blockIdx.x * blockDim.x + threadIdx.x;
    if (i < kB * kDh)
        out[(size_t)kB * kT * kDout + i] = g_hs[(size_t)kT * kB * kDh + i];
}

// ---------------- launch ------------------------------------------------------

extern "C" void kernel_launch(void* const* d_in, const int* in_sizes, int n_in,
                              void* d_out, int out_size) {
    (void)in_sizes; (void)n_in; (void)out_size;
    const float* inp = (const float*)d_in[0];
    const float* Wz  = (const float*)d_in[1];
    const float* bz  = (const float*)d_in[2];
    const float* Wr  = (const float*)d_in[3];
    const float* br  = (const float*)d_in[4];
    const float* Ws  = (const float*)d_in[5];
    const float* bs  = (const float*)d_in[6];
    const float* Wo  = (const float*)d_in[7];
    const float* bo  = (const float*)d_in[8];
    float* out = (float*)d_out;

    cudaFuncSetAttribute(recur_kernel, cudaFuncAttributeMaxDynamicSharedMemorySize,
                         (int)kSmemBytes);

    zero_h0_kernel<<<(kB * kDh + 255) / 256, 256>>>();
    prep_w_kernel<<<(3 * kKP * kDh + 255) / 256, 256>>>(Wz, Wr, Ws);
    prep_wx_kernel<<<(3 * kDh * kKPx + 255) / 256, 256>>>(Wz, Wr, Ws);
    prep_wo_kernel<<<(kDout * kKP + 255) / 256, 256>>>(Wo);
    prep_in_kernel<<<(kB * kT * kKPx + 255) / 256, 256>>>(inp);
    proj_x_kernel<<<dim3(kB * kT / 64, 3 * kDh / 64), 256>>>(bz, br, bs);
    recur_kernel<<<kNC, 512, kSmemBytes>>>();
    out_proj_kernel<<<dim3(kT, kDout / 64), 256>>>(bo, out);
    final_copy_kernel<<<(kB * kDh + 255) / 256, 256>>>(out);
}